// round 5
// baseline (speedup 1.0000x reference)
#include <cuda_runtime.h>
#include <cuda_bf16.h>
#include <cstdint>

#define BATCH 2
#define NC 4096
#define NF 16384
#define CC 256
#define CF 128
#define CO 256
#define KTOT 384  // CC + CF
#define NBLKF (NF / 128)

// ---------------- scratch (device globals; no allocations allowed) ----------
__device__ float g_Yc[BATCH * CO * NC];   // Wc @ Fc : [B, Co, Nc]
__device__ int   g_idx[BATCH * NF];
__device__ float g_ps [BATCH * CO * NBLKF];
__device__ float g_pss[BATCH * CO * NBLKF];

// ---------------- helpers ----------------------------------------------------
__device__ __forceinline__ uint32_t smem_u32(const void* p) {
    uint32_t a;
    asm("{ .reg .u64 t; cvta.to.shared.u64 t, %1; cvt.u32.u64 %0, t; }"
        : "=r"(a) : "l"(p));
    return a;
}

__device__ __forceinline__ void ldsm4(uint32_t (&r)[4], uint32_t addr) {
    asm volatile("ldmatrix.sync.aligned.m8n8.x4.shared.b16 {%0,%1,%2,%3}, [%4];"
                 : "=r"(r[0]), "=r"(r[1]), "=r"(r[2]), "=r"(r[3]) : "r"(addr));
}
__device__ __forceinline__ void ldsm4t(uint32_t (&r)[4], uint32_t addr) {
    asm volatile("ldmatrix.sync.aligned.m8n8.x4.trans.shared.b16 {%0,%1,%2,%3}, [%4];"
                 : "=r"(r[0]), "=r"(r[1]), "=r"(r[2]), "=r"(r[3]) : "r"(addr));
}
__device__ __forceinline__ void mma16816(float (&d)[4], const uint32_t (&a)[4],
                                         uint32_t b0, uint32_t b1) {
    asm volatile(
        "mma.sync.aligned.m16n8k16.row.col.f32.bf16.bf16.f32 "
        "{%0,%1,%2,%3}, {%4,%5,%6,%7}, {%8,%9}, {%0,%1,%2,%3};"
        : "+f"(d[0]), "+f"(d[1]), "+f"(d[2]), "+f"(d[3])
        : "r"(a[0]), "r"(a[1]), "r"(a[2]), "r"(a[3]), "r"(b0), "r"(b1));
}

// split two fp32 into packed-bf16x2 hi and lo words
__device__ __forceinline__ void split2(float x0, float x1, uint32_t& hi, uint32_t& lo) {
    __nv_bfloat16 h0 = __float2bfloat16(x0);
    __nv_bfloat16 h1 = __float2bfloat16(x1);
    float r0 = x0 - __bfloat162float(h0);
    float r1 = x1 - __bfloat162float(h1);
    __nv_bfloat162 hh;
    hh.x = h0; hh.y = h1;
    __nv_bfloat162 ll;
    ll.x = __float2bfloat16(r0); ll.y = __float2bfloat16(r1);
    hi = *(uint32_t*)&hh;
    lo = *(uint32_t*)&ll;
}

// ============================================================================
// K1: nearest coarse neighbor per fine point (unchanged, issue-bound ~20us)
// ============================================================================
__global__ void nn_kernel(const float* __restrict__ xyzc,
                          const float* __restrict__ xyzf) {
    __shared__ float4 sc[2048];
    const int b = blockIdx.y;
    const int f = blockIdx.x * 128 + threadIdx.x;
    const float* p = xyzf + ((size_t)b * NF + f) * 3;
    const float px = -2.0f * p[0];
    const float py = -2.0f * p[1];
    const float pz = -2.0f * p[2];
    float best = 3.4e38f;
    int bi = 0;
    const float* xb = xyzc + (size_t)b * NC * 3;
    for (int half = 0; half < 2; half++) {
        for (int j = threadIdx.x; j < 2048; j += 128) {
            const float* c = xb + (size_t)(half * 2048 + j) * 3;
            float x = c[0], y = c[1], z = c[2];
            sc[j] = make_float4(x, y, z, x * x + y * y + z * z);
        }
        __syncthreads();
        const int base = half * 2048;
#pragma unroll 4
        for (int j = 0; j < 2048; j += 2) {
            float4 c0 = sc[j];
            float4 c1 = sc[j + 1];
            float d0 = fmaf(px, c0.x, c0.w);
            d0 = fmaf(py, c0.y, d0);
            d0 = fmaf(pz, c0.z, d0);
            float d1 = fmaf(px, c1.x, c1.w);
            d1 = fmaf(py, c1.y, d1);
            d1 = fmaf(pz, c1.z, d1);
            float m = fminf(d0, d1);
            if (m < best) {
                best = m;
                bi = (d0 <= d1) ? (base + j) : (base + j + 1);
            }
        }
        __syncthreads();
    }
    g_idx[b * NF + f] = bi;
}

// ============================================================================
// HMMA bf16 split GEMM, double-buffered + software-pipelined.
// out[b,m,n] = sum_k W[m, WOFF+k] * F[b,k,n]; hi*hi + hi*lo + lo*hi in fp32.
// BM=BN=128, BK=32, 256 threads (8 warps, 4m x 2n), warp tile 32x64.
// Per k-iter: LDG(next) -> MMA(cur buf) -> cvt+STS(next -> other buf) -> bar.
// ============================================================================
#define AROW 40     // A tile row stride (bf16 elems): 80 B
#define BROW 136    // B tile row stride (bf16 elems): 272 B
#define OFF_AH 0
#define OFF_AL 10240
#define OFF_BH 20480
#define OFF_BL 29184
#define BUFSZ 37888
#define OSTR 132    // epilogue smem float stride
#define SMEM_BYTES (2 * BUFSZ)  // 75776; epilogue (67584) overlays both bufs

template <int N, int KDIM, int WOFF, bool GATHER>
__global__ __launch_bounds__(256) void hmma_gemm_kernel(
    const float* __restrict__ W, const float* __restrict__ F,
    float* __restrict__ dout) {
    extern __shared__ char smp[];
    const uint32_t sb = smem_u32(smp);
    __shared__ int sidx[128];
    constexpr int NCH = KDIM / 32;

    const int b = blockIdx.z;
    const int mBase = blockIdx.y * 128;
    const int nBase = blockIdx.x * 128;
    const int t = threadIdx.x;
    const int w = t >> 5;
    const int lid = t & 31;
    const int wm = (w >> 1) * 32;
    const int wn = (w & 1) * 64;

    if (GATHER && t < 128) sidx[t] = g_idx[b * NF + nBase + t];

    float c[2][8][4];
#pragma unroll
    for (int mt = 0; mt < 2; mt++)
#pragma unroll
        for (int nt = 0; nt < 8; nt++)
#pragma unroll
            for (int r = 0; r < 4; r++) c[mt][nt][r] = 0.f;

    const float* Wp = W + (size_t)mBase * KTOT + WOFF;
    const float* Fp = F + (size_t)b * KDIM * N + nBase;

    // load/stage thread mappings
    const int a_kq = (t & 7) * 4;
    const int a_m0 = t >> 3;
    const int b_n4 = (t & 31) * 4;
    const int b_k0 = t >> 5;

    // ldmatrix lane addresses
    const int a_row = (lid & 7) + ((lid >> 3) & 1) * 8;
    const int a_colb = (lid >> 4) * 8;
    const int b_row = (lid & 7) + ((lid >> 3) & 1) * 8;
    const int b_colb = (lid >> 4) * 8;

    float4 pa[4], pb[4];

    // --- prologue: load + stage k-chunk 0 into buf0
#pragma unroll
    for (int p = 0; p < 4; p++)
        pa[p] = *(const float4*)&Wp[(size_t)(a_m0 + 32 * p) * KTOT + a_kq];
#pragma unroll
    for (int p = 0; p < 4; p++)
        pb[p] = *(const float4*)&Fp[(size_t)(b_k0 + 8 * p) * N + b_n4];
    {
        char* buf = smp;
#pragma unroll
        for (int p = 0; p < 4; p++) {
            uint32_t h0, l0, h1, l1;
            split2(pa[p].x, pa[p].y, h0, l0);
            split2(pa[p].z, pa[p].w, h1, l1);
            char* dst = buf + ((a_m0 + 32 * p) * AROW + a_kq) * 2;
            *(uint2*)(dst + OFF_AH) = make_uint2(h0, h1);
            *(uint2*)(dst + OFF_AL) = make_uint2(l0, l1);
        }
#pragma unroll
        for (int p = 0; p < 4; p++) {
            uint32_t h0, l0, h1, l1;
            split2(pb[p].x, pb[p].y, h0, l0);
            split2(pb[p].z, pb[p].w, h1, l1);
            char* dst = buf + ((b_k0 + 8 * p) * BROW + b_n4) * 2;
            *(uint2*)(dst + OFF_BH) = make_uint2(h0, h1);
            *(uint2*)(dst + OFF_BL) = make_uint2(l0, l1);
        }
    }
    __syncthreads();

#pragma unroll
    for (int ck = 0; ck < NCH; ck++) {
        // --- issue next chunk's global loads (latency hidden behind MMAs)
        if (ck + 1 < NCH) {
            const int k0n = (ck + 1) * 32;
#pragma unroll
            for (int p = 0; p < 4; p++)
                pa[p] = *(const float4*)&Wp[(size_t)(a_m0 + 32 * p) * KTOT + k0n + a_kq];
#pragma unroll
            for (int p = 0; p < 4; p++)
                pb[p] = *(const float4*)&Fp[(size_t)(k0n + b_k0 + 8 * p) * N + b_n4];
        }

        // --- MMAs on current buffer
        const uint32_t cb = sb + (ck & 1) * BUFSZ;
#pragma unroll
        for (int k16 = 0; k16 < 2; k16++) {
            uint32_t ah[2][4], al[2][4], bh[4][4], bl[4][4];
#pragma unroll
            for (int mt = 0; mt < 2; mt++) {
                uint32_t ad = cb + ((wm + mt * 16 + a_row) * AROW + k16 * 16 + a_colb) * 2;
                ldsm4(ah[mt], ad + OFF_AH);
                ldsm4(al[mt], ad + OFF_AL);
            }
#pragma unroll
            for (int ng = 0; ng < 4; ng++) {
                uint32_t bd = cb + ((k16 * 16 + b_row) * BROW + wn + ng * 16 + b_colb) * 2;
                ldsm4t(bh[ng], bd + OFF_BH);
                ldsm4t(bl[ng], bd + OFF_BL);
            }
#pragma unroll
            for (int mt = 0; mt < 2; mt++)
#pragma unroll
                for (int nt = 0; nt < 8; nt++) {
                    const int ng = nt >> 1;
                    const int pr = (nt & 1) * 2;
                    mma16816(c[mt][nt], ah[mt], bh[ng][pr], bh[ng][pr + 1]);
                    mma16816(c[mt][nt], ah[mt], bl[ng][pr], bl[ng][pr + 1]);
                    mma16816(c[mt][nt], al[mt], bh[ng][pr], bh[ng][pr + 1]);
                }
        }

        // --- convert + stage next chunk into the other buffer
        if (ck + 1 < NCH) {
            char* buf = smp + ((ck + 1) & 1) * BUFSZ;
#pragma unroll
            for (int p = 0; p < 4; p++) {
                uint32_t h0, l0, h1, l1;
                split2(pa[p].x, pa[p].y, h0, l0);
                split2(pa[p].z, pa[p].w, h1, l1);
                char* dst = buf + ((a_m0 + 32 * p) * AROW + a_kq) * 2;
                *(uint2*)(dst + OFF_AH) = make_uint2(h0, h1);
                *(uint2*)(dst + OFF_AL) = make_uint2(l0, l1);
            }
#pragma unroll
            for (int p = 0; p < 4; p++) {
                uint32_t h0, l0, h1, l1;
                split2(pb[p].x, pb[p].y, h0, l0);
                split2(pb[p].z, pb[p].w, h1, l1);
                char* dst = buf + ((b_k0 + 8 * p) * BROW + b_n4) * 2;
                *(uint2*)(dst + OFF_BH) = make_uint2(h0, h1);
                *(uint2*)(dst + OFF_BL) = make_uint2(l0, l1);
            }
        }
        __syncthreads();
    }

    // ---- epilogue: accum -> smem [128][OSTR] -> coalesced global
    float* smOut = (float*)smp;
    {
        const int r_m = lid >> 2;
        const int cn = (lid & 3) * 2;
#pragma unroll
        for (int mt = 0; mt < 2; mt++)
#pragma unroll
            for (int nt = 0; nt < 8; nt++) {
                const int row = wm + mt * 16 + r_m;
                const int col = wn + nt * 8 + cn;
                *(float2*)&smOut[row * OSTR + col] =
                    make_float2(c[mt][nt][0], c[mt][nt][1]);
                *(float2*)&smOut[(row + 8) * OSTR + col] =
                    make_float2(c[mt][nt][2], c[mt][nt][3]);
            }
    }
    __syncthreads();

#pragma unroll 4
    for (int rr = 0; rr < 16; rr++) {
        const int r0 = w + rr * 8;
        const int m = mBase + r0;
        float4 v = *(float4*)&smOut[r0 * OSTR + lid * 4];
        if (GATHER) {
            const float* yc = g_Yc + ((size_t)b * CO + m) * NC;
            v.x += yc[sidx[lid * 4 + 0]];
            v.y += yc[sidx[lid * 4 + 1]];
            v.z += yc[sidx[lid * 4 + 2]];
            v.w += yc[sidx[lid * 4 + 3]];
            *(float4*)&dout[((size_t)b * CO + m) * NF + nBase + lid * 4] = v;
            float s = v.x + v.y + v.z + v.w;
            float ss = v.x * v.x + v.y * v.y + v.z * v.z + v.w * v.w;
#pragma unroll
            for (int off = 16; off > 0; off >>= 1) {
                s += __shfl_down_sync(0xffffffffu, s, off);
                ss += __shfl_down_sync(0xffffffffu, ss, off);
            }
            if (lid == 0) {
                g_ps [((size_t)b * CO + m) * NBLKF + blockIdx.x] = s;
                g_pss[((size_t)b * CO + m) * NBLKF + blockIdx.x] = ss;
            }
        } else {
            *(float4*)&g_Yc[((size_t)b * CO + m) * NC + nBase + lid * 4] = v;
        }
    }
}

// ============================================================================
// K4: fused BN-finish + normalize + relu. One block = 256 float4 of ONE channel.
// Each block deterministically re-reduces its channel's 256 partials (hot in L2),
// then normalizes its 4KB segment in place. Replaces stats2 + norm.
// ============================================================================
__global__ __launch_bounds__(256) void norm_fused_kernel(
    float* __restrict__ y, const float* __restrict__ gamma,
    const float* __restrict__ beta) {
    const int blk = blockIdx.x;
    const int o = (blk >> 4) & (CO - 1);
    const int t = threadIdx.x;
    const int w = t >> 5;
    const int lane = t & 31;

    // load this channel's 256 partials: p = (b<<7) | nblk
    size_t off = ((size_t)(t >> 7) * CO + o) * NBLKF + (t & 127);
    float s = g_ps[off];
    float ss = g_pss[off];
#pragma unroll
    for (int d = 16; d > 0; d >>= 1) {
        s += __shfl_down_sync(0xffffffffu, s, d);
        ss += __shfl_down_sync(0xffffffffu, ss, d);
    }
    __shared__ float as[8], as2[8], bc[2];
    if (lane == 0) {
        as[w] = s;
        as2[w] = ss;
    }
    __syncthreads();
    if (t == 0) {
        float S = 0.f, SS = 0.f;
#pragma unroll
        for (int i = 0; i < 8; i++) {
            S += as[i];
            SS += as2[i];
        }
        const float invn = 1.0f / (BATCH * NF);
        float mean = S * invn;
        float var = SS * invn - mean * mean;
        var = fmaxf(var, 0.0f);
        float r = rsqrtf(var + 1e-5f);
        float sc = gamma[o] * r;
        bc[0] = sc;
        bc[1] = beta[o] - mean * sc;
    }
    __syncthreads();
    const float sc = bc[0];
    const float sh = bc[1];

    float4* y4 = (float4*)y;
    const size_t i = (size_t)blk * 256 + t;
    float4 v = y4[i];
    v.x = fmaxf(fmaf(v.x, sc, sh), 0.0f);
    v.y = fmaxf(fmaf(v.y, sc, sh), 0.0f);
    v.z = fmaxf(fmaf(v.z, sc, sh), 0.0f);
    v.w = fmaxf(fmaf(v.w, sc, sh), 0.0f);
    y4[i] = v;
}

// ============================================================================
extern "C" void kernel_launch(void* const* d_in, const int* in_sizes, int n_in,
                              void* d_out, int out_size) {
    const float* xyzc  = (const float*)d_in[0];  // [2, 4096, 3]
    const float* fc    = (const float*)d_in[1];  // [2, 256, 4096]
    const float* xyzf  = (const float*)d_in[2];  // [2, 16384, 3]
    const float* ff    = (const float*)d_in[3];  // [2, 128, 16384]
    const float* W     = (const float*)d_in[4];  // [256, 384]
    const float* gamma = (const float*)d_in[5];  // [256]
    const float* beta  = (const float*)d_in[6];  // [256]
    float* out = (float*)d_out;                  // [2, 256, 16384]

    (void)in_sizes; (void)n_in; (void)out_size;

    static bool attr_done = false;
    if (!attr_done) {
        cudaFuncSetAttribute(hmma_gemm_kernel<NC, CC, 0, false>,
                             cudaFuncAttributeMaxDynamicSharedMemorySize, SMEM_BYTES);
        cudaFuncSetAttribute(hmma_gemm_kernel<NF, CF, CC, true>,
                             cudaFuncAttributeMaxDynamicSharedMemorySize, SMEM_BYTES);
        attr_done = true;
    }

    nn_kernel<<<dim3(NF / 128, BATCH), 128>>>(xyzc, xyzf);

    // Yc = Wc @ Fc (tensor cores, bf16 split)
    hmma_gemm_kernel<NC, CC, 0, false>
        <<<dim3(NC / 128, CO / 128, BATCH), 256, SMEM_BYTES>>>(W, fc, out);

    // y = Wf @ Ff + gather(Yc) (tensor cores, fused BN partials)
    hmma_gemm_kernel<NF, CF, CC, true>
        <<<dim3(NF / 128, CO / 128, BATCH), 256, SMEM_BYTES>>>(W, ff, out);

    // fused BN stats finish + normalize + relu
    norm_fused_kernel<<<BATCH * CO * NF / 1024, 256>>>(out, gamma, beta);
}